// round 9
// baseline (speedup 1.0000x reference)
#include <cuda_runtime.h>
#include <cstdint>

#define DINLINE __device__ __forceinline__

namespace {
constexpr int kTlen = 1024;
constexpr int kF = 64;
constexpr int kH = 256;
constexpr int kK = 320;          // K = H + F
constexpr int kNJ = 16;          // CTAs per barrier group (hidden stripes)
constexpr int kBT = 16;          // batch rows per CTA
constexpr int kNS = 16;          // k-slices (split-K)
constexpr int kKP = 10;          // f32x2 pairs per slice (20 k values)
constexpr int kThreads = 256;
constexpr int kCtas = 128;       // 8 batch stripes x 16 hidden stripes
constexpr int kSmemBytes = 120 * 1024;  // force 1 CTA/SM => all CTAs resident
}

__device__ float g_h[2][128 * 256];
__device__ unsigned g_cnt[8 * 64];  // one counter per group, 256B apart

__global__ void init_barriers_kernel() {
  if (threadIdx.x < 8) g_cnt[threadIdx.x * 64] = 0u;
}

DINLINE unsigned long long pack2(float lo, float hi) {
  unsigned long long r;
  asm("mov.b64 %0, {%1, %2};" : "=l"(r) : "f"(lo), "f"(hi));
  return r;
}
DINLINE void ffma2(unsigned long long& d, unsigned long long a, unsigned long long b) {
  asm("fma.rn.f32x2 %0, %1, %2, %0;" : "+l"(d) : "l"(a), "l"(b));
}
DINLINE float2 unpack2(unsigned long long v) {
  float lo, hi;
  asm("mov.b64 {%0, %1}, %2;" : "=f"(lo), "=f"(hi) : "l"(v));
  return make_float2(lo, hi);
}
DINLINE float sigmoidf_(float x) { return __fdividef(1.0f, 1.0f + __expf(-x)); }
DINLINE float tanhf_(float x) {
  const float e = __expf(2.0f * x);
  return 1.0f - __fdividef(2.0f, e + 1.0f);
}

__global__ void __launch_bounds__(kThreads, 1)
lstm_seq2seq_kernel(const float* __restrict__ ts,
                    const float* __restrict__ Wih_e, const float* __restrict__ Whh_e,
                    const float* __restrict__ b_e,
                    const float* __restrict__ Wih_d, const float* __restrict__ Whh_d,
                    const float* __restrict__ b_d,
                    const float* __restrict__ Wout, const float* __restrict__ bout,
                    float* __restrict__ out) {
  extern __shared__ float smem[];
  float* partial = smem;                     // [16 slices][16 b][64] col = j*4+gate
  float* wout_s = partial + kNS * kBT * 64;  // [4][256]
  float* bout_s = wout_s + 4 * kH;           // [4]

  const int tid = threadIdx.x;
  const int jstripe = blockIdx.x & (kNJ - 1);
  const int bstripe = blockIdx.x >> 4;

  const int slice = tid >> 4;   // 0..15  (GEMM k-slice)
  const int cg = tid & 15;      // 0..15  (local hidden col j in GEMM phase)
  const int bl = tid >> 4;      // update: local batch row
  const int jj = tid & 15;      // update: local hidden col

  unsigned* cnt = &g_cnt[bstripe * 64];
  unsigned barno = 0;           // maintained by tid 0 only

  // h0 = 0 for owned (b,j); stage W_out tile + b_out
  g_h[0][(bstripe * kBT + bl) * kH + jstripe * 16 + jj] = 0.0f;
  for (int idx = tid; idx < 4 * kH; idx += kThreads)
    wout_s[idx] = Wout[jstripe * 4 * kH + idx];
  if (tid < 4) bout_s[tid] = bout[jstripe * 4 + tid];

  unsigned long long w2[4][kKP];  // [gate][k-pair] weights, register-resident
  float bias[4];
  float cst = 0.0f;               // cell state, register-resident across ALL steps

  // cc = GATE index (0..3), local hidden col = cg  -> W row = cc*kH + j_global
  auto load_w = [&](const float* Wih, const float* Whh, const float* bv) {
#pragma unroll
    for (int cc = 0; cc < 4; ++cc) {
      const int row = cc * kH + jstripe * 16 + cg;
#pragma unroll
      for (int kp = 0; kp < kKP; ++kp) {
        const int k0 = slice * 20 + 2 * kp;
        float a, b;
        if (k0 < kH) { a = Whh[row * kH + k0];        b = Whh[row * kH + k0 + 1]; }
        else         { a = Wih[row * kF + (k0 - kH)]; b = Wih[row * kF + (k0 - kH) + 1]; }
        w2[cc][kp] = pack2(a, b);
      }
    }
    const int jg = jstripe * 16 + jj;
#pragma unroll
    for (int g = 0; g < 4; ++g) bias[g] = bv[g * kH + jg];
  };

  // monotonic single-counter barrier (counter zeroed by init kernel per launch)
  auto arrive = [&]() {
    __syncthreads();  // all h stores of this CTA issued
    if (tid == 0) {
      ++barno;
      // release-RED: orders all CTA writes (happens-before via syncthreads)
      asm volatile("red.release.gpu.global.add.u32 [%0], %1;"
                   :: "l"(cnt), "r"(1u) : "memory");
    }
  };
  auto wait = [&]() {
    if (tid == 0) {
      const unsigned target = (unsigned)kNJ * barno;
      unsigned v;
      do {
        asm volatile("ld.acquire.gpu.u32 %0, [%1];" : "=r"(v) : "l"(cnt));
      } while ((int)(v - target) < 0);
    }
    __syncthreads();
  };

  auto step = [&](int t, int buf, bool dec) {
    wait();  // h(t) visible at L2

    // GEMM operands straight from L2 (__ldcg): warp-broadcast coalesced,
    // warps own disjoint slices -> no redundant traffic. Each float4 is
    // purely h or purely x (k0 = 20*slice + 4q is 4-aligned, 256 boundary ok).
    const float* hb = g_h[buf] + bstripe * kBT * kH;
    const float* xb = ts + (size_t)(bstripe * kBT) * kTlen * kF + t * kF - kH;
    const int s20 = slice * 20;

#pragma unroll
    for (int bg = 0; bg < 4; ++bg) {
      unsigned long long acc[4][4];
#pragma unroll
      for (int bb = 0; bb < 4; ++bb)
#pragma unroll
        for (int cc = 0; cc < 4; ++cc) acc[bb][cc] = 0ull;
#pragma unroll
      for (int q = 0; q < 5; ++q) {
        const int k0 = s20 + 4 * q;
#pragma unroll
        for (int bb = 0; bb < 4; ++bb) {
          const int row = bg * 4 + bb;
          const float* p = (k0 < kH) ? (hb + row * kH + k0)
                                     : (xb + (size_t)row * kTlen * kF + k0);
          const float4 vv = __ldcg(reinterpret_cast<const float4*>(p));
          const unsigned long long v0 = pack2(vv.x, vv.y);
          const unsigned long long v1 = pack2(vv.z, vv.w);
#pragma unroll
          for (int cc = 0; cc < 4; ++cc) {
            ffma2(acc[bb][cc], v0, w2[cc][2 * q]);
            ffma2(acc[bb][cc], v1, w2[cc][2 * q + 1]);
          }
        }
      }
#pragma unroll
      for (int bb = 0; bb < 4; ++bb) {
        // gate-interleaved: cols cg*4..cg*4+3 hold gates 0..3 of local j=cg
        const float2 f0 = unpack2(acc[bb][0]);
        const float2 f1 = unpack2(acc[bb][1]);
        const float2 f2 = unpack2(acc[bb][2]);
        const float2 f3 = unpack2(acc[bb][3]);
        *reinterpret_cast<float4*>(
            partial + (slice * kBT + bg * 4 + bb) * 64 + cg * 4) =
            make_float4(f0.x + f0.y, f1.x + f1.y, f2.x + f2.y, f3.x + f3.y);
      }
    }
    __syncthreads();

    // reduce 16 slices (dual accumulator, one float4 per slice) + cell update
    {
      const float4* p4 = reinterpret_cast<const float4*>(partial);
      const int idx = bl * 16 + jj;
      float4 s0 = p4[idx];
      float4 s1 = p4[256 + idx];
#pragma unroll
      for (int sl = 2; sl < kNS; sl += 2) {
        const float4 a = p4[sl * 256 + idx];
        const float4 b = p4[(sl + 1) * 256 + idx];
        s0.x += a.x; s0.y += a.y; s0.z += a.z; s0.w += a.w;
        s1.x += b.x; s1.y += b.y; s1.z += b.z; s1.w += b.w;
      }
      const float ig = sigmoidf_(s0.x + s1.x + bias[0]);
      const float fg = sigmoidf_(s0.y + s1.y + bias[1]);
      const float gg = tanhf_(s0.z + s1.z + bias[2]);
      const float og = sigmoidf_(s0.w + s1.w + bias[3]);
      cst = fg * cst + ig * gg;
      const float hv = og * tanhf_(cst);
      g_h[buf ^ 1][(bstripe * kBT + bl) * kH + jstripe * 16 + jj] = hv;
    }
    arrive();  // publish h(t+1); projection below is off the serial path

    if (dec) {
      // out_t = h_pre @ Wout^T + bout — h_t read from L2 (g_h[buf] untouched)
      const int o = tid >> 2, p = tid & 3;
      const int ob = o >> 2, ofi = o & 3;
      const float4* v4 =
          reinterpret_cast<const float4*>(hb + ob * kH + p * 64);
      const float4* w4 =
          reinterpret_cast<const float4*>(wout_s + ofi * kH + p * 64);
      float s = 0.0f;
#pragma unroll
      for (int i = 0; i < 16; ++i) {
        const float4 a = __ldcg(v4 + i), b = w4[i];
        s += a.x * b.x + a.y * b.y + a.z * b.z + a.w * b.w;
      }
      s += __shfl_xor_sync(0xffffffffu, s, 1);
      s += __shfl_xor_sync(0xffffffffu, s, 2);
      if (p == 0)
        out[((bstripe * kBT + ob) * kTlen + t) * kF + jstripe * 4 + ofi] =
            s + bout_s[ofi];
    }
  };

  load_w(Wih_e, Whh_e, b_e);
  arrive();  // publish h0

  for (int t = 0; t < kTlen; ++t) step(t, t & 1, false);

  load_w(Wih_d, Whh_d, b_d);
  for (int i = 0; i < kTlen; ++i) step(kTlen - 1 - i, i & 1, true);
}

extern "C" void kernel_launch(void* const* d_in, const int* in_sizes, int n_in,
                              void* d_out, int out_size) {
  cudaFuncSetAttribute(lstm_seq2seq_kernel,
                       cudaFuncAttributeMaxDynamicSharedMemorySize, kSmemBytes);
  init_barriers_kernel<<<1, 32>>>();
  lstm_seq2seq_kernel<<<kCtas, kThreads, kSmemBytes>>>(
      (const float*)d_in[0], (const float*)d_in[1], (const float*)d_in[2],
      (const float*)d_in[3], (const float*)d_in[4], (const float*)d_in[5],
      (const float*)d_in[6], (const float*)d_in[7], (const float*)d_in[8],
      (float*)d_out);
}

// round 10
// speedup vs baseline: 1.1375x; 1.1375x over previous
#include <cuda_runtime.h>
#include <cstdint>

#define DINLINE __device__ __forceinline__

namespace {
constexpr int kTlen = 1024;
constexpr int kF = 64;
constexpr int kH = 256;
constexpr int kK = 320;          // K = H + F (vec = [h | x])
constexpr int kNJ = 16;          // CTAs per barrier group (hidden stripes)
constexpr int kBT = 16;          // batch rows per CTA
constexpr int kNS = 16;          // k-slices (split-K)
constexpr int kKP = 10;          // f32x2 pairs per slice (20 k values)
constexpr int kThreads = 256;
constexpr int kCtas = 128;       // 8 batch stripes x 16 hidden stripes
constexpr int kSmemBytes = 120 * 1024;  // force 1 CTA/SM => all CTAs resident
}

__device__ float g_h[2][128 * 256];
__device__ unsigned g_cnt[8 * 64];  // arrival counters, one per group, 256B apart
__device__ unsigned g_rel[8 * 64];  // release flags,    one per group, 256B apart

__global__ void init_barriers_kernel() {
  if (threadIdx.x < 8) {
    g_cnt[threadIdx.x * 64] = 0u;
    g_rel[threadIdx.x * 64] = 0u;
  }
}

DINLINE unsigned long long pack2(float lo, float hi) {
  unsigned long long r;
  asm("mov.b64 %0, {%1, %2};" : "=l"(r) : "f"(lo), "f"(hi));
  return r;
}
DINLINE void ffma2(unsigned long long& d, unsigned long long a, unsigned long long b) {
  asm("fma.rn.f32x2 %0, %1, %2, %0;" : "+l"(d) : "l"(a), "l"(b));
}
DINLINE float2 unpack2(unsigned long long v) {
  float lo, hi;
  asm("mov.b64 {%0, %1}, %2;" : "=f"(lo), "=f"(hi) : "l"(v));
  return make_float2(lo, hi);
}
DINLINE float sigmoidf_(float x) { return __fdividef(1.0f, 1.0f + __expf(-x)); }
DINLINE float tanhf_(float x) {
  const float e = __expf(2.0f * x);
  return 1.0f - __fdividef(2.0f, e + 1.0f);
}

__global__ void __launch_bounds__(kThreads, 1)
lstm_seq2seq_kernel(const float* __restrict__ ts,
                    const float* __restrict__ Wih_e, const float* __restrict__ Whh_e,
                    const float* __restrict__ b_e,
                    const float* __restrict__ Wih_d, const float* __restrict__ Whh_d,
                    const float* __restrict__ b_d,
                    const float* __restrict__ Wout, const float* __restrict__ bout,
                    float* __restrict__ out) {
  extern __shared__ float smem[];
  float* vec = smem;                         // [16][320]  vec = [h_t | x_t]
  float* partial = smem + kBT * kK;          // [16 slices][16 b][64] col = j*4+gate
  float* wout_s = partial + kNS * kBT * 64;  // [4][256]
  float* bout_s = wout_s + 4 * kH;           // [4]

  const int tid = threadIdx.x;
  const int jstripe = blockIdx.x & (kNJ - 1);
  const int bstripe = blockIdx.x >> 4;

  const int slice = tid >> 4;   // 0..15  (GEMM k-slice)
  const int cg = tid & 15;      // 0..15  (local hidden col j in GEMM phase)
  const int bl = tid >> 4;      // update: local batch row
  const int jj = tid & 15;      // update: local hidden col

  unsigned* cnt = &g_cnt[bstripe * 64];
  unsigned* rel = &g_rel[bstripe * 64];
  unsigned barno = 0;

  // h0 = 0 for owned (b,j); stage W_out tile + b_out
  g_h[0][(bstripe * kBT + bl) * kH + jstripe * 16 + jj] = 0.0f;
  for (int idx = tid; idx < 4 * kH; idx += kThreads)
    wout_s[idx] = Wout[jstripe * 4 * kH + idx];
  if (tid < 4) bout_s[tid] = bout[jstripe * 4 + tid];

  unsigned long long w2[4][kKP];  // [gate][k-pair] weights, register-resident
  float bias[4];
  float cst = 0.0f;               // cell state, register-resident across ALL steps

  // cc = GATE index (0..3), local hidden col = cg  -> W row = cc*kH + j_global
  auto load_w = [&](const float* Wih, const float* Whh, const float* bv) {
#pragma unroll
    for (int cc = 0; cc < 4; ++cc) {
      const int row = cc * kH + jstripe * 16 + cg;
#pragma unroll
      for (int kp = 0; kp < kKP; ++kp) {
        const int k0 = slice * 20 + 2 * kp;
        float a, b;
        if (k0 < kH) { a = Whh[row * kH + k0];        b = Whh[row * kH + k0 + 1]; }
        else         { a = Wih[row * kF + (k0 - kH)]; b = Wih[row * kF + (k0 - kH) + 1]; }
        w2[cc][kp] = pack2(a, b);
      }
    }
    const int jg = jstripe * 16 + jj;
#pragma unroll
    for (int g = 0; g < 4; ++g) bias[g] = bv[g * kH + jg];
  };

  // two-line barrier: arrivals RMW line A; LAST arriver publishes step number
  // on line B with st.release; everyone polls line B (read-only broadcast,
  // no RMW contention). Monotonic counters, zeroed per launch -> replay-safe.
  auto arrive = [&]() {
    __syncthreads();  // all h stores of this CTA issued
    if (tid == 0) {
      ++barno;
      unsigned old;
      asm volatile("atom.add.acq_rel.gpu.global.u32 %0, [%1], %2;"
                   : "=r"(old) : "l"(cnt), "r"(1u) : "memory");
      if (old == (unsigned)kNJ * barno - 1u)
        asm volatile("st.release.gpu.global.u32 [%0], %1;"
                     :: "l"(rel), "r"(barno) : "memory");
    }
  };
  auto wait = [&]() {
    if (tid == 0) {
      unsigned v;
      do {
        asm volatile("ld.acquire.gpu.global.u32 %0, [%1];" : "=r"(v) : "l"(rel));
      } while ((int)(v - barno) < 0);
    }
    __syncthreads();
  };

  auto step = [&](int t, int buf, bool dec) {
    // prefetch x(t): LDG latency hides under the barrier spin
    const int xrow = tid >> 4, xcol = tid & 15;
    const float4 vx = reinterpret_cast<const float4*>(
        ts + (((bstripe * kBT + xrow) * kTlen + t) * kF))[xcol];

    wait();  // h(t) visible

    // stage vec = [h_t | x_t] into smem (coalesced)
    {
      const int r0 = tid >> 6, kc = tid & 63;
#pragma unroll
      for (int p = 0; p < 4; ++p) {
        const int row = p * 4 + r0;
        float4 v = reinterpret_cast<const float4*>(
            g_h[buf] + (bstripe * kBT + row) * kH)[kc];
        reinterpret_cast<float4*>(vec + row * kK)[kc] = v;
      }
      reinterpret_cast<float4*>(vec + xrow * kK + kH)[xcol] = vx;
    }
    __syncthreads();

    // gate GEMM partials: float4 operand loads, f32x2 FMAs, weights in regs
    const float4* vec4 = reinterpret_cast<const float4*>(vec);
#pragma unroll
    for (int bg = 0; bg < 4; ++bg) {
      unsigned long long acc[4][4];
#pragma unroll
      for (int bb = 0; bb < 4; ++bb)
#pragma unroll
        for (int cc = 0; cc < 4; ++cc) acc[bb][cc] = 0ull;
#pragma unroll
      for (int q = 0; q < 5; ++q) {   // 5 float4 = 20 k values per slice
#pragma unroll
        for (int bb = 0; bb < 4; ++bb) {
          const float4 vv = vec4[(bg * 4 + bb) * (kK / 4) + slice * 5 + q];
          const unsigned long long v0 = pack2(vv.x, vv.y);
          const unsigned long long v1 = pack2(vv.z, vv.w);
#pragma unroll
          for (int cc = 0; cc < 4; ++cc) {
            ffma2(acc[bb][cc], v0, w2[cc][2 * q]);
            ffma2(acc[bb][cc], v1, w2[cc][2 * q + 1]);
          }
        }
      }
#pragma unroll
      for (int bb = 0; bb < 4; ++bb) {
        // gate-interleaved: cols cg*4..cg*4+3 hold gates 0..3 of local j=cg
        const float2 f0 = unpack2(acc[bb][0]);
        const float2 f1 = unpack2(acc[bb][1]);
        const float2 f2 = unpack2(acc[bb][2]);
        const float2 f3 = unpack2(acc[bb][3]);
        *reinterpret_cast<float4*>(
            partial + (slice * kBT + bg * 4 + bb) * 64 + cg * 4) =
            make_float4(f0.x + f0.y, f1.x + f1.y, f2.x + f2.y, f3.x + f3.y);
      }
    }
    __syncthreads();

    // reduce 16 slices (dual accumulator, one float4 per slice) + cell update
    {
      const float4* p4 = reinterpret_cast<const float4*>(partial);
      const int idx = bl * 16 + jj;
      float4 s0 = p4[idx];
      float4 s1 = p4[256 + idx];
#pragma unroll
      for (int sl = 2; sl < kNS; sl += 2) {
        const float4 a = p4[sl * 256 + idx];
        const float4 b = p4[(sl + 1) * 256 + idx];
        s0.x += a.x; s0.y += a.y; s0.z += a.z; s0.w += a.w;
        s1.x += b.x; s1.y += b.y; s1.z += b.z; s1.w += b.w;
      }
      const float ig = sigmoidf_(s0.x + s1.x + bias[0]);
      const float fg = sigmoidf_(s0.y + s1.y + bias[1]);
      const float gg = tanhf_(s0.z + s1.z + bias[2]);
      const float og = sigmoidf_(s0.w + s1.w + bias[3]);
      cst = fg * cst + ig * gg;
      const float hv = og * tanhf_(cst);
      g_h[buf ^ 1][(bstripe * kBT + bl) * kH + jstripe * 16 + jj] = hv;
    }
    arrive();  // publish h(t+1); projection below is off the serial path

    if (dec) {
      // out_t = h_pre @ Wout^T + bout — vec still holds h_t
      const int o = tid >> 2, p = tid & 3;
      const int ob = o >> 2, ofi = o & 3;
      const float4* v4 = reinterpret_cast<const float4*>(vec + ob * kK + p * 64);
      const float4* w4 = reinterpret_cast<const float4*>(wout_s + ofi * kH + p * 64);
      float s = 0.0f;
#pragma unroll
      for (int i = 0; i < 16; ++i) {
        const float4 a = v4[i], b = w4[i];
        s += a.x * b.x + a.y * b.y + a.z * b.z + a.w * b.w;
      }
      s += __shfl_xor_sync(0xffffffffu, s, 1);
      s += __shfl_xor_sync(0xffffffffu, s, 2);
      if (p == 0)
        out[((bstripe * kBT + ob) * kTlen + t) * kF + jstripe * 4 + ofi] =
            s + bout_s[ofi];
    }
  };

  load_w(Wih_e, Whh_e, b_e);
  arrive();  // publish h0

  for (int t = 0; t < kTlen; ++t) step(t, t & 1, false);

  load_w(Wih_d, Whh_d, b_d);
  for (int i = 0; i < kTlen; ++i) step(kTlen - 1 - i, i & 1, true);
}

extern "C" void kernel_launch(void* const* d_in, const int* in_sizes, int n_in,
                              void* d_out, int out_size) {
  cudaFuncSetAttribute(lstm_seq2seq_kernel,
                       cudaFuncAttributeMaxDynamicSharedMemorySize, kSmemBytes);
  init_barriers_kernel<<<1, 32>>>();
  lstm_seq2seq_kernel<<<kCtas, kThreads, kSmemBytes>>>(
      (const float*)d_in[0], (const float*)d_in[1], (const float*)d_in[2],
      (const float*)d_in[3], (const float*)d_in[4], (const float*)d_in[5],
      (const float*)d_in[6], (const float*)d_in[7], (const float*)d_in[8],
      (float*)d_out);
}

// round 11
// speedup vs baseline: 1.2658x; 1.1127x over previous
#include <cuda_runtime.h>
#include <cstdint>

#define DINLINE __device__ __forceinline__

namespace {
constexpr int kTlen = 1024;
constexpr int kF = 64;
constexpr int kH = 256;
constexpr int kVRow = 324;   // padded vec row stride (floats) = 81 float4
constexpr int kBT = 16;      // batch rows per CTA
constexpr int kNS = 16;      // k-slices; slice s = h[16s..16s+15] ++ x[4s..4s+3]
constexpr int kThreads = 256;
constexpr int kCtas = 128;   // 8 batch stripes x 16 hidden stripes
constexpr int kSmemBytes = 120 * 1024;  // force 1 CTA/SM
}

__device__ float g_h[2][128 * 256];
__device__ unsigned g_flag[128 * 32];  // one monotonic flag per CTA, 128B apart

__global__ void init_barriers_kernel() {
  if (threadIdx.x < 128) g_flag[threadIdx.x * 32] = 0u;
}

DINLINE unsigned long long pack2(float lo, float hi) {
  unsigned long long r;
  asm("mov.b64 %0, {%1, %2};" : "=l"(r) : "f"(lo), "f"(hi));
  return r;
}
DINLINE void ffma2(unsigned long long& d, unsigned long long a, unsigned long long b) {
  asm("fma.rn.f32x2 %0, %1, %2, %0;" : "+l"(d) : "l"(a), "l"(b));
}
DINLINE float2 unpack2(unsigned long long v) {
  float lo, hi;
  asm("mov.b64 {%0, %1}, %2;" : "=f"(lo), "=f"(hi) : "l"(v));
  return make_float2(lo, hi);
}
DINLINE float sigmoidf_(float x) { return __fdividef(1.0f, 1.0f + __expf(-x)); }
DINLINE float tanhf_(float x) {
  const float e = __expf(2.0f * x);
  return 1.0f - __fdividef(2.0f, e + 1.0f);
}

__global__ void __launch_bounds__(kThreads, 1)
lstm_seq2seq_kernel(const float* __restrict__ ts,
                    const float* __restrict__ Wih_e, const float* __restrict__ Whh_e,
                    const float* __restrict__ b_e,
                    const float* __restrict__ Wih_d, const float* __restrict__ Whh_d,
                    const float* __restrict__ b_d,
                    const float* __restrict__ Wout, const float* __restrict__ bout,
                    float* __restrict__ out) {
  extern __shared__ float smem[];
  float* vec = smem;                          // [16][324] interleaved [16h|4x]*16
  float* partial = smem + kBT * kVRow;        // [16 slices][16 b][64] col=j*4+gate
  float* wout_s = partial + kNS * kBT * 64;   // [4][256]
  float* bout_s = wout_s + 4 * kH;            // [4]

  const int tid = threadIdx.x;
  const int warp = tid >> 5, lane = tid & 31;
  const int jstripe = blockIdx.x & 15;
  const int bstripe = blockIdx.x >> 4;

  const int slice = tid >> 4;   // 0..15 (GEMM k-slice; warp w owns slices 2w,2w+1)
  const int cg = tid & 15;      // 0..15 (local hidden col j)
  const int bl = tid >> 4;      // update: local batch row
  const int jj = tid & 15;      // update: local hidden col

  // staging role: lane -> (row, slice)
  const int srow = lane >> 1;            // 0..15
  const int sslice = 2 * warp + (lane & 1);
  const unsigned* pflag = &g_flag[(bstripe * 16 + sslice) * 32];
  unsigned* myflag = &g_flag[blockIdx.x * 32];

  // prologue: publish h0 = 0 for own block; stage W_out tile + b_out
  g_h[0][(bstripe * kBT + bl) * kH + jstripe * 16 + jj] = 0.0f;
  for (int idx = tid; idx < 4 * kH; idx += kThreads)
    wout_s[idx] = Wout[jstripe * 4 * kH + idx];
  if (tid < 4) bout_s[tid] = bout[jstripe * 4 + tid];
  __syncthreads();
  if (tid == 0)
    asm volatile("st.release.gpu.u32 [%0], %1;" :: "l"(myflag), "r"(1u) : "memory");

  unsigned long long w2[4][10];  // [gate][k-pair], interleaved-k, register-resident
  float bias[4];
  float cst = 0.0f;              // cell state, register-resident across all steps

  // interleaved k mapping: slice s, kp<8 -> h col s*16+2kp; kp 8,9 -> x col s*4+2(kp-8)
  auto load_w = [&](const float* Wih, const float* Whh, const float* bv) {
#pragma unroll
    for (int cc = 0; cc < 4; ++cc) {
      const int row = cc * kH + jstripe * 16 + cg;
#pragma unroll
      for (int kp = 0; kp < 8; ++kp) {
        const int k = slice * 16 + 2 * kp;
        w2[cc][kp] = pack2(Whh[row * kH + k], Whh[row * kH + k + 1]);
      }
#pragma unroll
      for (int kp = 8; kp < 10; ++kp) {
        const int k = slice * 4 + 2 * (kp - 8);
        w2[cc][kp] = pack2(Wih[row * kF + k], Wih[row * kF + k + 1]);
      }
    }
    const int jg = jstripe * 16 + jj;
#pragma unroll
    for (int g = 0; g < 4; ++g) bias[g] = bv[g * kH + jg];
  };

  const float4* vec4 = reinterpret_cast<const float4*>(vec);

  auto step = [&](unsigned gstep, int tt, bool dec) {
    const int buf = (int)(gstep & 1u);

    // pre-stage x(tt) into own slice's x-slot (flag-independent)
    {
      const float4 vx = *reinterpret_cast<const float4*>(
          ts + ((size_t)(bstripe * kBT + srow) * kTlen + tt) * kF + sslice * 4);
      *reinterpret_cast<float4*>(vec + srow * kVRow + sslice * 20 + 16) = vx;
    }

    // per-warp wait: only this warp's two producers
    {
      const unsigned tgt = gstep + 1u;
      unsigned v; bool ok;
      do {
        asm volatile("ld.acquire.gpu.u32 %0, [%1];" : "=r"(v) : "l"(pflag));
        ok = (int)(v - tgt) >= 0;
      } while (!__all_sync(0xffffffffu, ok));
    }

    // stage own producer's h-block: 16 h cols for row srow
    {
      const float4* src = reinterpret_cast<const float4*>(
          g_h[buf] + (bstripe * kBT + srow) * kH + sslice * 16);
      const float4 h0 = src[0], h1 = src[1], h2 = src[2], h3 = src[3];
      float4* dst = reinterpret_cast<float4*>(vec + srow * kVRow + sslice * 20);
      dst[0] = h0; dst[1] = h1; dst[2] = h2; dst[3] = h3;
    }
    __syncwarp();  // GEMM below reads only this warp's staged slices

    // gate GEMM (own slice): float4 LDS, f32x2 FMAs, weights in registers
#pragma unroll
    for (int bg = 0; bg < 4; ++bg) {
      unsigned long long acc[4][4];
#pragma unroll
      for (int bb = 0; bb < 4; ++bb)
#pragma unroll
        for (int cc = 0; cc < 4; ++cc) acc[bb][cc] = 0ull;
#pragma unroll
      for (int q = 0; q < 5; ++q) {   // q<4: h pairs, q==4: x pairs
#pragma unroll
        for (int bb = 0; bb < 4; ++bb) {
          const float4 vv = vec4[(bg * 4 + bb) * (kVRow / 4) + slice * 5 + q];
          const unsigned long long v0 = pack2(vv.x, vv.y);
          const unsigned long long v1 = pack2(vv.z, vv.w);
#pragma unroll
          for (int cc = 0; cc < 4; ++cc) {
            ffma2(acc[bb][cc], v0, w2[cc][2 * q]);
            ffma2(acc[bb][cc], v1, w2[cc][2 * q + 1]);
          }
        }
      }
#pragma unroll
      for (int bb = 0; bb < 4; ++bb) {
        const float2 f0 = unpack2(acc[bb][0]);
        const float2 f1 = unpack2(acc[bb][1]);
        const float2 f2 = unpack2(acc[bb][2]);
        const float2 f3 = unpack2(acc[bb][3]);
        *reinterpret_cast<float4*>(
            partial + (slice * kBT + bg * 4 + bb) * 64 + cg * 4) =
            make_float4(f0.x + f0.y, f1.x + f1.y, f2.x + f2.y, f3.x + f3.y);
      }
    }
    __syncthreads();

    // reduce 16 slices (one float4 per slice) + LSTM cell update
    {
      const float4* p4 = reinterpret_cast<const float4*>(partial);
      const int idx = bl * 16 + jj;
      float4 s = p4[idx];
#pragma unroll
      for (int sl = 1; sl < kNS; ++sl) {
        const float4 v = p4[sl * 256 + idx];
        s.x += v.x; s.y += v.y; s.z += v.z; s.w += v.w;
      }
      const float ig = sigmoidf_(s.x + bias[0]);
      const float fg = sigmoidf_(s.y + bias[1]);
      const float gg = tanhf_(s.z + bias[2]);
      const float og = sigmoidf_(s.w + bias[3]);
      cst = fg * cst + ig * gg;
      const float hv = og * tanhf_(cst);
      g_h[buf ^ 1][(bstripe * kBT + bl) * kH + jstripe * 16 + jj] = hv;
    }
    __syncthreads();
    if (tid == 0) {
      const unsigned pub = gstep + 2u;
      asm volatile("st.release.gpu.u32 [%0], %1;" :: "l"(myflag), "r"(pub)
                   : "memory");
    }

    if (dec) {
      // out_t = h_pre @ Wout^T + bout — vec holds h_t (interleaved layout)
      const int o = tid >> 2, p = tid & 3;
      const int ob = o >> 2, ofi = o & 3;
      float s = 0.0f;
#pragma unroll
      for (int si = 0; si < 4; ++si) {
        const int sl = p * 4 + si;
        const float4* v4 =
            reinterpret_cast<const float4*>(vec + ob * kVRow + sl * 20);
        const float4* w4 =
            reinterpret_cast<const float4*>(wout_s + ofi * kH + sl * 16);
#pragma unroll
        for (int i = 0; i < 4; ++i) {
          const float4 a = v4[i], b = w4[i];
          s += a.x * b.x + a.y * b.y + a.z * b.z + a.w * b.w;
        }
      }
      s += __shfl_xor_sync(0xffffffffu, s, 1);
      s += __shfl_xor_sync(0xffffffffu, s, 2);
      if (p == 0)
        out[((bstripe * kBT + ob) * kTlen + tt) * kF + jstripe * 4 + ofi] =
            s + bout_s[ofi];
      __syncthreads();  // vec fully read before any warp stages next step
    }
  };

  load_w(Wih_e, Whh_e, b_e);
  for (int t = 0; t < kTlen; ++t) step((unsigned)t, t, false);

  load_w(Wih_d, Whh_d, b_d);
  for (int i = 0; i < kTlen; ++i)
    step((unsigned)(kTlen + i), kTlen - 1 - i, true);
}

extern "C" void kernel_launch(void* const* d_in, const int* in_sizes, int n_in,
                              void* d_out, int out_size) {
  cudaFuncSetAttribute(lstm_seq2seq_kernel,
                       cudaFuncAttributeMaxDynamicSharedMemorySize, kSmemBytes);
  init_barriers_kernel<<<1, 128>>>();
  lstm_seq2seq_kernel<<<kCtas, kThreads, kSmemBytes>>>(
      (const float*)d_in[0], (const float*)d_in[1], (const float*)d_in[2],
      (const float*)d_in[3], (const float*)d_in[4], (const float*)d_in[5],
      (const float*)d_in[6], (const float*)d_in[7], (const float*)d_in[8],
      (float*)d_out);
}

// round 13
// speedup vs baseline: 1.2867x; 1.0165x over previous
#include <cuda_runtime.h>
#include <cstdint>

#define DINLINE __device__ __forceinline__

namespace {
constexpr int kTlen = 1024;
constexpr int kF = 64;
constexpr int kH = 256;
constexpr int kVRow = 324;   // padded vec row stride (floats)
constexpr int kVBuf = 16 * kVRow;  // one vec buffer (16 rows)
constexpr int kBT = 16;      // batch rows per CTA
constexpr int kNS = 16;      // k-slices; slice s = h[16s..16s+15] ++ x[4s..4s+3]
constexpr int kThreads = 256;
constexpr int kCtas = 128;   // 8 batch stripes x 16 hidden stripes
constexpr int kSmemBytes = 120 * 1024;  // force 1 CTA/SM
}

__device__ float g_h[2][128 * 256];
__device__ unsigned g_flag[128 * 32];  // one monotonic flag per CTA, 128B apart

__global__ void init_barriers_kernel() {
  if (threadIdx.x < 128) g_flag[threadIdx.x * 32] = 0u;
}

DINLINE unsigned long long pack2(float lo, float hi) {
  unsigned long long r;
  asm("mov.b64 %0, {%1, %2};" : "=l"(r) : "f"(lo), "f"(hi));
  return r;
}
DINLINE void ffma2(unsigned long long& d, unsigned long long a, unsigned long long b) {
  asm("fma.rn.f32x2 %0, %1, %2, %0;" : "+l"(d) : "l"(a), "l"(b));
}
DINLINE float2 unpack2(unsigned long long v) {
  float lo, hi;
  asm("mov.b64 {%0, %1}, %2;" : "=f"(lo), "=f"(hi) : "l"(v));
  return make_float2(lo, hi);
}
DINLINE float tanh_fast(float x) {
  float y;
  asm("tanh.approx.f32 %0, %1;" : "=f"(y) : "f"(x));
  return y;
}
DINLINE float sigmoid_fast(float x) {
  return 0.5f * tanh_fast(0.5f * x) + 0.5f;
}

__global__ void __launch_bounds__(kThreads, 1)
lstm_seq2seq_kernel(const float* __restrict__ ts,
                    const float* __restrict__ Wih_e, const float* __restrict__ Whh_e,
                    const float* __restrict__ b_e,
                    const float* __restrict__ Wih_d, const float* __restrict__ Whh_d,
                    const float* __restrict__ b_d,
                    const float* __restrict__ Wout, const float* __restrict__ bout,
                    float* __restrict__ out) {
  extern __shared__ float smem[];
  float* vecs = smem;                          // [2][16][324] interleaved
  float* partial = smem + 2 * kVBuf;           // [16 slices][16 b][64] col=j*4+gate
  float* wout_s = partial + kNS * kBT * 64;    // [4][256]
  float* bout_s = wout_s + 4 * kH;             // [4]

  const int tid = threadIdx.x;
  const int warp = tid >> 5, lane = tid & 31;
  const int jstripe = blockIdx.x & 15;
  const int bstripe = blockIdx.x >> 4;

  const int slice = tid >> 4;   // 0..15 (GEMM k-slice; warp w owns slices 2w,2w+1)
  const int cg = tid & 15;      // 0..15 (local hidden col j)
  const int bl = tid >> 4;      // update: local batch row
  const int jj = tid & 15;      // update: local hidden col

  // staging role: lane -> (row, slice)
  const int srow = lane >> 1;            // 0..15
  const int sslice = 2 * warp + (lane & 1);
  const unsigned* pflag = &g_flag[(bstripe * 16 + sslice) * 32];
  unsigned* myflag = &g_flag[blockIdx.x * 32];

  // prologue: publish h0 = 0 for own block; stage W_out tile + b_out
  g_h[0][(bstripe * kBT + bl) * kH + jstripe * 16 + jj] = 0.0f;
  for (int idx = tid; idx < 4 * kH; idx += kThreads)
    wout_s[idx] = Wout[jstripe * 4 * kH + idx];
  if (tid < 4) bout_s[tid] = bout[jstripe * 4 + tid];
  __syncthreads();
  if (tid == 0)
    asm volatile("st.release.gpu.u32 [%0], %1;" :: "l"(myflag), "r"(1u) : "memory");

  unsigned long long w2[4][10];  // [gate][k-pair], interleaved-k, registers
  float bias[4];
  float cst = 0.0f;              // cell state, register-resident across all steps

  // interleaved k: slice s, kp<8 -> h col s*16+2kp; kp 8,9 -> x col s*4+2(kp-8)
  auto load_w = [&](const float* Wih, const float* Whh, const float* bv) {
#pragma unroll
    for (int cc = 0; cc < 4; ++cc) {
      const int row = cc * kH + jstripe * 16 + cg;
#pragma unroll
      for (int kp = 0; kp < 8; ++kp) {
        const int k = slice * 16 + 2 * kp;
        w2[cc][kp] = pack2(Whh[row * kH + k], Whh[row * kH + k + 1]);
      }
#pragma unroll
      for (int kp = 8; kp < 10; ++kp) {
        const int k = slice * 4 + 2 * (kp - 8);
        w2[cc][kp] = pack2(Wih[row * kF + k], Wih[row * kF + k + 1]);
      }
    }
    const int jg = jstripe * 16 + jj;
#pragma unroll
    for (int g = 0; g < 4; ++g) bias[g] = bv[g * kH + jg];
  };

  auto step = [&](unsigned gstep, int tt, bool dec) {
    const int buf = (int)(gstep & 1u);
    float* vec = vecs + buf * kVBuf;
    const float4* vec4 = reinterpret_cast<const float4*>(vec);

    // pre-stage x(tt) into own slice's x-slot (flag-independent)
    {
      const float4 vx = *reinterpret_cast<const float4*>(
          ts + ((size_t)(bstripe * kBT + srow) * kTlen + tt) * kF + sslice * 4);
      *reinterpret_cast<float4*>(vec + srow * kVRow + sslice * 20 + 16) = vx;
    }

    // per-warp wait: only this warp's two producers
    {
      const unsigned tgt = gstep + 1u;
      unsigned v; bool ok;
      do {
        asm volatile("ld.acquire.gpu.u32 %0, [%1];" : "=r"(v) : "l"(pflag));
        ok = (int)(v - tgt) >= 0;
      } while (!__all_sync(0xffffffffu, ok));
    }

    // stage own producer's h-block: 16 h cols for row srow
    {
      const float4* src = reinterpret_cast<const float4*>(
          g_h[buf] + (bstripe * kBT + srow) * kH + sslice * 16);
      const float4 h0 = src[0], h1 = src[1], h2 = src[2], h3 = src[3];
      float4* dst = reinterpret_cast<float4*>(vec + srow * kVRow + sslice * 20);
      dst[0] = h0; dst[1] = h1; dst[2] = h2; dst[3] = h3;
    }
    __syncwarp();  // GEMM below reads only this warp's staged slices

    // gate GEMM (own slice): float4 LDS, f32x2 FMAs, weights in registers
#pragma unroll
    for (int bg = 0; bg < 4; ++bg) {
      unsigned long long acc[4][4];
#pragma unroll
      for (int bb = 0; bb < 4; ++bb)
#pragma unroll
        for (int cc = 0; cc < 4; ++cc) acc[bb][cc] = 0ull;
#pragma unroll
      for (int q = 0; q < 5; ++q) {   // q<4: h pairs, q==4: x pairs
#pragma unroll
        for (int bb = 0; bb < 4; ++bb) {
          const float4 vv = vec4[(bg * 4 + bb) * (kVRow / 4) + slice * 5 + q];
          const unsigned long long v0 = pack2(vv.x, vv.y);
          const unsigned long long v1 = pack2(vv.z, vv.w);
#pragma unroll
          for (int cc = 0; cc < 4; ++cc) {
            ffma2(acc[bb][cc], v0, w2[cc][2 * q]);
            ffma2(acc[bb][cc], v1, w2[cc][2 * q + 1]);
          }
        }
      }
#pragma unroll
      for (int bb = 0; bb < 4; ++bb) {
        const float2 f0 = unpack2(acc[bb][0]);
        const float2 f1 = unpack2(acc[bb][1]);
        const float2 f2 = unpack2(acc[bb][2]);
        const float2 f3 = unpack2(acc[bb][3]);
        *reinterpret_cast<float4*>(
            partial + (slice * kBT + bg * 4 + bb) * 64 + cg * 4) =
            make_float4(f0.x + f0.y, f1.x + f1.y, f2.x + f2.y, f3.x + f3.y);
      }
    }
    __syncthreads();

    // reduce 16 slices (dual accumulator, one float4 per slice) + cell update
    {
      const float4* p4 = reinterpret_cast<const float4*>(partial);
      const int idx = bl * 16 + jj;
      float4 s0 = p4[idx];
      float4 s1 = p4[256 + idx];
#pragma unroll
      for (int sl = 2; sl < kNS; sl += 2) {
        const float4 a = p4[sl * 256 + idx];
        const float4 b = p4[(sl + 1) * 256 + idx];
        s0.x += a.x; s0.y += a.y; s0.z += a.z; s0.w += a.w;
        s1.x += b.x; s1.y += b.y; s1.z += b.z; s1.w += b.w;
      }
      const float ig = sigmoid_fast(s0.x + s1.x + bias[0]);
      const float fg = sigmoid_fast(s0.y + s1.y + bias[1]);
      const float gg = tanh_fast(s0.z + s1.z + bias[2]);
      const float og = sigmoid_fast(s0.w + s1.w + bias[3]);
      cst = fg * cst + ig * gg;
      const float hv = og * tanh_fast(cst);
      g_h[buf ^ 1][(bstripe * kBT + bl) * kH + jstripe * 16 + jj] = hv;
    }
    __syncthreads();
    if (tid == 0) {
      const unsigned pub = gstep + 2u;
      asm volatile("st.release.gpu.u32 [%0], %1;" :: "l"(myflag), "r"(pub)
                   : "memory");
    }

    if (dec) {
      // out_t = h_pre @ Wout^T + bout — reads THIS step's vec buffer;
      // next step stages into the other buffer, so no trailing sync needed.
      const int o = tid >> 2, p = tid & 3;
      const int ob = o >> 2, ofi = o & 3;
      float s = 0.0f;
#pragma unroll
      for (int si = 0; si < 4; ++si) {
        const int sl = p * 4 + si;
        const float4* v4 =
            reinterpret_cast<const float4*>(vec + ob * kVRow + sl * 20);
        const float4* w4 =
            reinterpret_cast<const float4*>(wout_s + ofi * kH + sl * 16);
#pragma unroll
        for (int i = 0; i < 4; ++i) {
          const float4 a = v4[i], b = w4[i];
          s += a.x * b.x + a.y * b.y + a.z * b.z + a.w * b.w;
        }
      }
      s += __shfl_xor_sync(0xffffffffu, s, 1);
      s += __shfl_xor_sync(0xffffffffu, s, 2);
      if (p == 0)
        out[((bstripe * kBT + ob) * kTlen + tt) * kF + jstripe * 4 + ofi] =
            s + bout_s[ofi];
    }
  };

  load_w(Wih_e, Whh_e, b_e);
  for (int t = 0; t < kTlen; ++t) step((unsigned)t, t, false);

  load_w(Wih_d, Whh_d, b_d);
  for (int i = 0; i < kTlen; ++i)
    step((unsigned)(kTlen + i), kTlen - 1 - i, true);
}

extern "C" void kernel_launch(void* const* d_in, const int* in_sizes, int n_in,
                              void* d_out, int out_size) {
  cudaFuncSetAttribute(lstm_seq2seq_kernel,
                       cudaFuncAttributeMaxDynamicSharedMemorySize, kSmemBytes);
  init_barriers_kernel<<<1, 128>>>();
  lstm_seq2seq_kernel<<<kCtas, kThreads, kSmemBytes>>>(
      (const float*)d_in[0], (const float*)d_in[1], (const float*)d_in[2],
      (const float*)d_in[3], (const float*)d_in[4], (const float*)d_in[5],
      (const float*)d_in[6], (const float*)d_in[7], (const float*)d_in[8],
      (float*)d_out);
}

// round 14
// speedup vs baseline: 1.3058x; 1.0148x over previous
#include <cuda_runtime.h>
#include <cstdint>

#define DINLINE __device__ __forceinline__

namespace {
constexpr int kTlen = 1024;
constexpr int kF = 64;
constexpr int kH = 256;
constexpr int kVRow = 324;   // padded vec row stride (floats)
constexpr int kVBuf = 16 * kVRow;  // one vec buffer (16 rows)
constexpr int kBT = 16;      // batch rows per CTA
constexpr int kNS = 16;      // k-slices; slice s = h[16s..16s+15] ++ x[4s..4s+3]
constexpr int kThreads = 256;
constexpr int kCtas = 128;   // 8 batch stripes x 16 hidden stripes
constexpr int kSmemBytes = 120 * 1024;  // force 1 CTA/SM
}

// h stored as per-producer PACKED tiles: g_h[buf][cta][b_local*16 + j_local]
__device__ float g_h[2][128 * 256];
__device__ unsigned g_flag[128 * 32];  // one monotonic flag per CTA, 128B apart

__global__ void init_barriers_kernel() {
  if (threadIdx.x < 128) g_flag[threadIdx.x * 32] = 0u;
}

DINLINE unsigned long long pack2(float lo, float hi) {
  unsigned long long r;
  asm("mov.b64 %0, {%1, %2};" : "=l"(r) : "f"(lo), "f"(hi));
  return r;
}
DINLINE void ffma2(unsigned long long& d, unsigned long long a, unsigned long long b) {
  asm("fma.rn.f32x2 %0, %1, %2, %0;" : "+l"(d) : "l"(a), "l"(b));
}
DINLINE float2 unpack2(unsigned long long v) {
  float lo, hi;
  asm("mov.b64 {%0, %1}, %2;" : "=f"(lo), "=f"(hi) : "l"(v));
  return make_float2(lo, hi);
}
DINLINE float tanh_fast(float x) {
  float y;
  asm("tanh.approx.f32 %0, %1;" : "=f"(y) : "f"(x));
  return y;
}
DINLINE float sigmoid_fast(float x) {
  return 0.5f * tanh_fast(0.5f * x) + 0.5f;
}

__global__ void __launch_bounds__(kThreads, 1)
lstm_seq2seq_kernel(const float* __restrict__ ts,
                    const float* __restrict__ Wih_e, const float* __restrict__ Whh_e,
                    const float* __restrict__ b_e,
                    const float* __restrict__ Wih_d, const float* __restrict__ Whh_d,
                    const float* __restrict__ b_d,
                    const float* __restrict__ Wout, const float* __restrict__ bout,
                    float* __restrict__ out) {
  extern __shared__ float smem[];
  float* vecs = smem;                          // [2][16][324] interleaved
  float* partial = smem + 2 * kVBuf;           // [16 slices][16 b][64] col=j*4+gate
  float* wout_s = partial + kNS * kBT * 64;    // [4][256]
  float* bout_s = wout_s + 4 * kH;             // [4]

  const int tid = threadIdx.x;
  const int warp = tid >> 5, lane = tid & 31;
  const int jstripe = blockIdx.x & 15;
  const int bstripe = blockIdx.x >> 4;

  const int slice = tid >> 4;   // 0..15 (GEMM k-slice; warp w owns slices 2w,2w+1)
  const int cg = tid & 15;      // 0..15 (local hidden col j)
  const int bl = tid >> 4;      // update: local batch row
  const int jj = tid & 15;      // update: local hidden col

  // x staging role: lane -> (row, slice)
  const int srow = lane >> 1;
  const int sslice = 2 * warp + (lane & 1);
  const unsigned* pflag = &g_flag[(bstripe * 16 + sslice) * 32];
  unsigned* myflag = &g_flag[blockIdx.x * 32];

  // prologue: publish h0 = 0 tile; stage W_out tile + b_out
  g_h[0][blockIdx.x * 256 + tid] = 0.0f;
  for (int idx = tid; idx < 4 * kH; idx += kThreads)
    wout_s[idx] = Wout[jstripe * 4 * kH + idx];
  if (tid < 4) bout_s[tid] = bout[jstripe * 4 + tid];
  __syncthreads();
  if (tid == 0)
    asm volatile("st.release.gpu.u32 [%0], %1;" :: "l"(myflag), "r"(1u) : "memory");

  unsigned long long w2[4][10];  // [gate][k-pair], interleaved-k, registers
  float bias[4];
  float cst = 0.0f;              // cell state, register-resident across all steps

  // interleaved k: slice s, kp<8 -> h col s*16+2kp; kp 8,9 -> x col s*4+2(kp-8)
  auto load_w = [&](const float* Wih, const float* Whh, const float* bv) {
#pragma unroll
    for (int cc = 0; cc < 4; ++cc) {
      const int row = cc * kH + jstripe * 16 + cg;
#pragma unroll
      for (int kp = 0; kp < 8; ++kp) {
        const int k = slice * 16 + 2 * kp;
        w2[cc][kp] = pack2(Whh[row * kH + k], Whh[row * kH + k + 1]);
      }
#pragma unroll
      for (int kp = 8; kp < 10; ++kp) {
        const int k = slice * 4 + 2 * (kp - 8);
        w2[cc][kp] = pack2(Wih[row * kF + k], Wih[row * kF + k + 1]);
      }
    }
    const int jg = jstripe * 16 + jj;
#pragma unroll
    for (int g = 0; g < 4; ++g) bias[g] = bv[g * kH + jg];
  };

  auto step = [&](unsigned gstep, int tt, bool dec) {
    const int buf = (int)(gstep & 1u);
    float* vec = vecs + buf * kVBuf;
    const float4* vec4 = reinterpret_cast<const float4*>(vec);

    // pre-stage x(tt) into own slice's x-slot (flag-independent)
    {
      const float4 vx = *reinterpret_cast<const float4*>(
          ts + ((size_t)(bstripe * kBT + srow) * kTlen + tt) * kF + sslice * 4);
      *reinterpret_cast<float4*>(vec + srow * kVRow + sslice * 20 + 16) = vx;
    }

    // per-warp wait: only this warp's two producers
    {
      const unsigned tgt = gstep + 1u;
      unsigned v; bool ok;
      do {
        asm volatile("ld.acquire.gpu.u32 %0, [%1];" : "=r"(v) : "l"(pflag));
        ok = (int)(v - tgt) >= 0;
      } while (!__all_sync(0xffffffffu, ok));
    }

    // stage this warp's two producer tiles (fully coalesced: 2KB contiguous)
    {
      const float4* t0 = reinterpret_cast<const float4*>(
          g_h[buf] + (bstripe * 16 + 2 * warp) * 256);
#pragma unroll
      for (int k = 0; k < 4; ++k) {
        const int flat = k * 32 + lane;        // 0..127 over 2 tiles
        const int s = 2 * warp + (flat >> 6);  // tile -> slice
        const int r = (flat >> 2) & 15;        // b row within tile
        const int c = flat & 3;                // float4 within row
        const float4 v = t0[flat];
        *reinterpret_cast<float4*>(vec + r * kVRow + s * 20 + c * 4) = v;
      }
    }
    __syncwarp();  // GEMM below reads only this warp's staged slices

    // gate GEMM (own slice): split accumulators guarantee FFMA2 independence
#pragma unroll
    for (int bg = 0; bg < 4; ++bg) {
      unsigned long long accA[4][4], accB[4][4];
#pragma unroll
      for (int bb = 0; bb < 4; ++bb)
#pragma unroll
        for (int cc = 0; cc < 4; ++cc) { accA[bb][cc] = 0ull; accB[bb][cc] = 0ull; }
#pragma unroll
      for (int q = 0; q < 5; ++q) {   // q<4: h pairs, q==4: x pairs
#pragma unroll
        for (int bb = 0; bb < 4; ++bb) {
          const float4 vv = vec4[(bg * 4 + bb) * (kVRow / 4) + slice * 5 + q];
          const unsigned long long v0 = pack2(vv.x, vv.y);
          const unsigned long long v1 = pack2(vv.z, vv.w);
#pragma unroll
          for (int cc = 0; cc < 4; ++cc) ffma2(accA[bb][cc], v0, w2[cc][2 * q]);
#pragma unroll
          for (int cc = 0; cc < 4; ++cc) ffma2(accB[bb][cc], v1, w2[cc][2 * q + 1]);
        }
      }
#pragma unroll
      for (int bb = 0; bb < 4; ++bb) {
        float r[4];
#pragma unroll
        for (int cc = 0; cc < 4; ++cc) {
          const float2 fa = unpack2(accA[bb][cc]);
          const float2 fb = unpack2(accB[bb][cc]);
          r[cc] = (fa.x + fa.y) + (fb.x + fb.y);
        }
        *reinterpret_cast<float4*>(
            partial + (slice * kBT + bg * 4 + bb) * 64 + cg * 4) =
            make_float4(r[0], r[1], r[2], r[3]);
      }
    }
    __syncthreads();

    // reduce 16 slices (dual accumulator, one float4 per slice) + cell update
    {
      const float4* p4 = reinterpret_cast<const float4*>(partial);
      const int idx = bl * 16 + jj;
      float4 s0 = p4[idx];
      float4 s1 = p4[256 + idx];
#pragma unroll
      for (int sl = 2; sl < kNS; sl += 2) {
        const float4 a = p4[sl * 256 + idx];
        const float4 b = p4[(sl + 1) * 256 + idx];
        s0.x += a.x; s0.y += a.y; s0.z += a.z; s0.w += a.w;
        s1.x += b.x; s1.y += b.y; s1.z += b.z; s1.w += b.w;
      }
      const float ig = sigmoid_fast(s0.x + s1.x + bias[0]);
      const float fg = sigmoid_fast(s0.y + s1.y + bias[1]);
      const float gg = tanh_fast(s0.z + s1.z + bias[2]);
      const float og = sigmoid_fast(s0.w + s1.w + bias[3]);
      cst = fg * cst + ig * gg;
      const float hv = og * tanh_fast(cst);
      // publish h(t+1) tile PACKED: g_h[buf^1][cta][bl*16 + jj] (coalesced)
      g_h[buf ^ 1][blockIdx.x * 256 + bl * 16 + jj] = hv;
    }
    __syncthreads();
    if (tid == 0) {
      const unsigned pub = gstep + 2u;
      asm volatile("st.release.gpu.u32 [%0], %1;" :: "l"(myflag), "r"(pub)
                   : "memory");
    }

    if (dec) {
      // out_t = h_pre @ Wout^T + bout — reads THIS step's vec buffer;
      // next step stages into the other buffer, so no trailing sync needed.
      const int o = tid >> 2, p = tid & 3;
      const int ob = o >> 2, ofi = o & 3;
      float s = 0.0f;
#pragma unroll
      for (int si = 0; si < 4; ++si) {
        const int sl = p * 4 + si;
        const float4* v4 =
            reinterpret_cast<const float4*>(vec + ob * kVRow + sl * 20);
        const float4* w4 =
            reinterpret_cast<const float4*>(wout_s + ofi * kH + sl * 16);
#pragma unroll
        for (int i = 0; i < 4; ++i) {
          const float4 a = v4[i], b = w4[i];
          s += a.x * b.x + a.y * b.y + a.z * b.z + a.w * b.w;
        }
      }
      s += __shfl_xor_sync(0xffffffffu, s, 1);
      s += __shfl_xor_sync(0xffffffffu, s, 2);
      if (p == 0)
        out[((bstripe * kBT + ob) * kTlen + tt) * kF + jstripe * 4 + ofi] =
            s + bout_s[ofi];
    }
  };

  load_w(Wih_e, Whh_e, b_e);
  for (int t = 0; t < kTlen; ++t) step((unsigned)t, t, false);

  load_w(Wih_d, Whh_d, b_d);
  for (int i = 0; i < kTlen; ++i)
    step((unsigned)(kTlen + i), kTlen - 1 - i, true);
}

extern "C" void kernel_launch(void* const* d_in, const int* in_sizes, int n_in,
                              void* d_out, int out_size) {
  cudaFuncSetAttribute(lstm_seq2seq_kernel,
                       cudaFuncAttributeMaxDynamicSharedMemorySize, kSmemBytes);
  init_barriers_kernel<<<1, 128>>>();
  lstm_seq2seq_kernel<<<kCtas, kThreads, kSmemBytes>>>(
      (const float*)d_in[0], (const float*)d_in[1], (const float*)d_in[2],
      (const float*)d_in[3], (const float*)d_in[4], (const float*)d_in[5],
      (const float*)d_in[6], (const float*)d_in[7], (const float*)d_in[8],
      (float*)d_out);
}